// round 14
// baseline (speedup 1.0000x reference)
#include <cuda_runtime.h>
#include <cuda_bf16.h>
#include <cstdint>

// ---------------------------------------------------------------------------
// Problem constants
// ---------------------------------------------------------------------------
#define MTOK   8192          // B_*S tokens
#define D      4096
#define NADAPT 8
#define RANK   16
#define NR     128           // NADAPT*RANK
#define KTOT   4224          // D + NR, concatenated GEMM K
#define LSCALE 2.0f          // ALPHA/RANK
#define KS     4             // K-split factor for gemm_h

// ---------------------------------------------------------------------------
// Global scratch (static __device__ arrays: allocation-guard-safe)
// ---------------------------------------------------------------------------
__device__ __align__(128) float          g_Hp[KS * MTOK * NR];
__device__ __align__(128) __nv_bfloat16  g_Xh[(size_t)MTOK * KTOT];
__device__ __align__(128) __nv_bfloat16  g_Xl[(size_t)MTOK * KTOT];
__device__ __align__(128) __nv_bfloat16  g_Bh[(size_t)D    * KTOT];
__device__ __align__(128) __nv_bfloat16  g_Bl[(size_t)D    * KTOT];

// ---------------------------------------------------------------------------
// Helpers
// ---------------------------------------------------------------------------
__device__ __forceinline__ void cp_async16(void* smem, const void* gmem) {
    uint32_t sa = (uint32_t)__cvta_generic_to_shared(smem);
    asm volatile("cp.async.cg.shared.global [%0], [%1], 16;\n" :: "r"(sa), "l"(gmem));
}
__device__ __forceinline__ void cp_async16_s(uint32_t sa, const void* gmem) {
    asm volatile("cp.async.cg.shared.global [%0], [%1], 16;\n" :: "r"(sa), "l"(gmem));
}
__device__ __forceinline__ void cp_commit() { asm volatile("cp.async.commit_group;\n"); }
__device__ __forceinline__ void cp_wait0()  { asm volatile("cp.async.wait_group 0;\n"); }
__device__ __forceinline__ void cp_wait1()  { asm volatile("cp.async.wait_group 1;\n"); }

// bf16 split of two fp32 values: hi = truncate-to-bf16 (exact residual), lo = rn-bf16.
__device__ __forceinline__ void split2(float f0, float f1, uint32_t& hi, uint32_t& lo) {
    uint32_t u0 = __float_as_uint(f0), u1 = __float_as_uint(f1);
    asm("prmt.b32 %0, %1, %2, 0x7632;" : "=r"(hi) : "r"(u0), "r"(u1));
    float h0 = __uint_as_float(u0 & 0xffff0000u);
    float h1 = __uint_as_float(u1 & 0xffff0000u);
    float l0 = f0 - h0;
    float l1 = f1 - h1;
    asm("cvt.rn.bf16x2.f32 %0, %1, %2;" : "=r"(lo) : "f"(l1), "f"(l0));
}

__device__ __forceinline__ void mma_bf16(float c[4],
                                         uint32_t a0, uint32_t a1, uint32_t a2, uint32_t a3,
                                         uint32_t b0, uint32_t b1) {
    asm volatile(
        "mma.sync.aligned.m16n8k16.row.col.f32.bf16.bf16.f32 "
        "{%0,%1,%2,%3}, {%4,%5,%6,%7}, {%8,%9}, {%0,%1,%2,%3};\n"
        : "+f"(c[0]), "+f"(c[1]), "+f"(c[2]), "+f"(c[3])
        : "r"(a0), "r"(a1), "r"(a2), "r"(a3), "r"(b0), "r"(b1));
}

__device__ __forceinline__ void ldsm4(uint32_t& r0, uint32_t& r1, uint32_t& r2, uint32_t& r3,
                                      uint32_t addr) {
    asm volatile("ldmatrix.sync.aligned.m8n8.x4.shared.b16 {%0,%1,%2,%3}, [%4];"
                 : "=r"(r0), "=r"(r1), "=r"(r2), "=r"(r3) : "r"(addr));
}

// ---------------------------------------------------------------------------
// Kernel 1: H partial = (x @ A_all^T) * coef over a 1024-wide K slice
// grid (KS, 64), 256 threads (unchanged)
// ---------------------------------------------------------------------------
#define BM 128
#define BN 128
#define BK 16
#define SROW 24

__global__ __launch_bounds__(256)
void gemm_h(const float* __restrict__ X, const float* __restrict__ loraA,
            const float* __restrict__ lw) {
    __shared__ float Xs[2][BM * SROW];
    __shared__ float Ws[2][BN * SROW];

    const int tid = threadIdx.x;
    const int m0  = blockIdx.y * BM;
    const int ksp = blockIdx.x;
    const int wid = tid >> 5, lane = tid & 31;
    const int wm  = wid >> 2, wn = wid & 3;
    const int g   = lane >> 2, tig = lane & 3;

    float acc[4][4][4];
#pragma unroll
    for (int mt = 0; mt < 4; mt++)
#pragma unroll
        for (int nt = 0; nt < 4; nt++)
#pragma unroll
            for (int i = 0; i < 4; i++) acc[mt][nt][i] = 0.0f;

    const int lr = tid >> 2;
    const int lc = (tid & 3) * 4;

    auto issue = [&](int kt, int buf) {
        const float* ga = X + (size_t)m0 * D + kt * BK;
        const float* gb = loraA + kt * BK;
#pragma unroll
        for (int p = 0; p < 2; p++) {
            int r = p * 64 + lr;
            cp_async16(&Xs[buf][r * SROW + lc], ga + (size_t)r * D + lc);
            cp_async16(&Ws[buf][r * SROW + lc], gb + (size_t)r * D + lc);
        }
        cp_commit();
    };

    const int kt0 = ksp * (D / BK / KS);
    const int kt1 = kt0 + (D / BK / KS);

    issue(kt0, 0);
    cp_wait0();
    __syncthreads();

    for (int kt = kt0; kt < kt1; kt++) {
        const int cur = kt & 1;
        if (kt + 1 < kt1) issue(kt + 1, cur ^ 1);

        const float* Xc = Xs[cur];
        const float* Wc = Ws[cur];
        uint32_t bh[4][2], bl[4][2];
#pragma unroll
        for (int nt = 0; nt < 4; nt++) {
            const float* bb = &Wc[(wn * 32 + nt * 8 + g) * SROW + 2 * tig];
            float2 v0 = *(const float2*)bb;
            float2 v1 = *(const float2*)(bb + 8);
            split2(v0.x, v0.y, bh[nt][0], bl[nt][0]);
            split2(v1.x, v1.y, bh[nt][1], bl[nt][1]);
        }
#pragma unroll
        for (int mt = 0; mt < 4; mt++) {
            const float* ar = &Xc[(wm * 64 + mt * 16 + g) * SROW + 2 * tig];
            float2 u0 = *(const float2*)ar;
            float2 u1 = *(const float2*)(ar + 8 * SROW);
            float2 u2 = *(const float2*)(ar + 8);
            float2 u3 = *(const float2*)(ar + 8 * SROW + 8);
            uint32_t ah[4], al[4];
            split2(u0.x, u0.y, ah[0], al[0]);
            split2(u1.x, u1.y, ah[1], al[1]);
            split2(u2.x, u2.y, ah[2], al[2]);
            split2(u3.x, u3.y, ah[3], al[3]);
#pragma unroll
            for (int nt = 0; nt < 4; nt++)
                mma_bf16(acc[mt][nt], ah[0], ah[1], ah[2], ah[3], bh[nt][0], bh[nt][1]);
#pragma unroll
            for (int nt = 0; nt < 4; nt++)
                mma_bf16(acc[mt][nt], al[0], al[1], al[2], al[3], bh[nt][0], bh[nt][1]);
#pragma unroll
            for (int nt = 0; nt < 4; nt++)
                mma_bf16(acc[mt][nt], ah[0], ah[1], ah[2], ah[3], bl[nt][0], bl[nt][1]);
        }
        cp_wait0();
        __syncthreads();
    }

    float* Hp = g_Hp + (size_t)ksp * MTOK * NR;
#pragma unroll
    for (int mt = 0; mt < 4; mt++) {
        const int row = m0 + wm * 64 + mt * 16 + g;
#pragma unroll
        for (int nt = 0; nt < 4; nt++) {
            const int col = wn * 32 + nt * 8 + 2 * tig;
            const float c = LSCALE * __ldg(&lw[col >> 4]);
            float2 v0 = make_float2(acc[mt][nt][0] * c, acc[mt][nt][1] * c);
            float2 v1 = make_float2(acc[mt][nt][2] * c, acc[mt][nt][3] * c);
            *(float2*)&Hp[(size_t)row * NR + col]       = v0;
            *(float2*)&Hp[(size_t)(row + 8) * NR + col] = v1;
        }
    }
}

// ---------------------------------------------------------------------------
// Kernel 2: convert [x | sum(Hp)] -> g_Xh / g_Xl
// ---------------------------------------------------------------------------
__global__ __launch_bounds__(256)
void convert_x(const float* __restrict__ x) {
    size_t idx = (size_t)blockIdx.x * 256 + threadIdx.x;
    size_t e   = idx * 4;
    int m = (int)(e / KTOT);
    int k = (int)(e % KTOT);
    float4 v;
    if (k < D) {
        v = *(const float4*)&x[(size_t)m * D + k];
    } else {
        size_t off = (size_t)m * NR + (k - D);
        float4 p0 = *(const float4*)&g_Hp[off];
        float4 p1 = *(const float4*)&g_Hp[(size_t)1 * MTOK * NR + off];
        float4 p2 = *(const float4*)&g_Hp[(size_t)2 * MTOK * NR + off];
        float4 p3 = *(const float4*)&g_Hp[(size_t)3 * MTOK * NR + off];
        v.x = (p0.x + p1.x) + (p2.x + p3.x);
        v.y = (p0.y + p1.y) + (p2.y + p3.y);
        v.z = (p0.z + p1.z) + (p2.z + p3.z);
        v.w = (p0.w + p1.w) + (p2.w + p3.w);
    }
    uint32_t h0, l0, h1, l1;
    split2(v.x, v.y, h0, l0);
    split2(v.z, v.w, h1, l1);
    *(uint2*)&g_Xh[(size_t)m * KTOT + k] = make_uint2(h0, h1);
    *(uint2*)&g_Xl[(size_t)m * KTOT + k] = make_uint2(l0, l1);
}

// ---------------------------------------------------------------------------
// Kernel 3: convert [W | B_all] -> g_Bh / g_Bl
// ---------------------------------------------------------------------------
__global__ __launch_bounds__(256)
void convert_b(const float* __restrict__ W, const float* __restrict__ loraB) {
    size_t idx = (size_t)blockIdx.x * 256 + threadIdx.x;
    size_t e   = idx * 4;
    int n = (int)(e / KTOT);
    int k = (int)(e % KTOT);
    float4 v;
    if (k < D) {
        v = *(const float4*)&W[(size_t)n * D + k];
    } else {
        int na = (k - D) >> 4;
        int r  = (k - D) & 15;
        v = *(const float4*)&loraB[((size_t)na * D + n) * RANK + r];
    }
    uint32_t h0, l0, h1, l1;
    split2(v.x, v.y, h0, l0);
    split2(v.z, v.w, h1, l1);
    *(uint2*)&g_Bh[(size_t)n * KTOT + k] = make_uint2(h0, h1);
    *(uint2*)&g_Bl[(size_t)n * KTOT + k] = make_uint2(l0, l1);
}

// ---------------------------------------------------------------------------
// Kernel 4: main GEMM, 3-stage cp.async pipeline + XOR swizzle.
//   R11 config with ONE barrier per iteration:
//     wait_group(1) -> syncthreads -> issue(kt+2) -> compute(kt)
//   The post-compute barrier is redundant: stage (buf+2)%3 written by issue
//   was last read in iteration kt-1, and every thread passing the top barrier
//   of iteration kt has finished iteration kt-1. Loads now overlap compute.
// ---------------------------------------------------------------------------
#define BKB    32
#define ROWB   64                         // bytes per row (32 bf16)
#define PLB    (128 * ROWB)               // 8192 B per plane
#define STGB   (4 * PLB)                  // 32768 B per stage
#define NSTG   3
#define SMEM_MAIN (NSTG * STGB)           // 98304 bytes

__global__ __launch_bounds__(256)
void gemm_mainp(const float* __restrict__ bias, float* __restrict__ out) {
    extern __shared__ __align__(128) char sm[];
    const uint32_t sbase = (uint32_t)__cvta_generic_to_shared(sm);

    const int tid = threadIdx.x;
    const int m0  = blockIdx.y * BM;
    const int n0  = blockIdx.x * BN;
    const int wid = tid >> 5, lane = tid & 31;
    const int wm  = wid >> 2, wn = wid & 3;
    const int g   = lane >> 2, tig = lane & 3;

    float acc[4][4][4];
#pragma unroll
    for (int mt = 0; mt < 4; mt++)
#pragma unroll
        for (int nt = 0; nt < 4; nt++)
#pragma unroll
            for (int i = 0; i < 4; i++) acc[mt][nt][i] = 0.0f;

    const int lr = tid >> 2;           // 0..63 row (2 passes -> 128)
    const int c0 = tid & 3;            // 16B chunk index within 64B row

    const __nv_bfloat16* gXh = g_Xh + (size_t)m0 * KTOT;
    const __nv_bfloat16* gXl = g_Xl + (size_t)m0 * KTOT;
    const __nv_bfloat16* gBh = g_Bh + (size_t)n0 * KTOT;
    const __nv_bfloat16* gBl = g_Bl + (size_t)n0 * KTOT;

    // LDSM lane addressing (swizzled). p(r) = (r>>1)&3 invariant under +16/+64.
    const int l  = lane;
    const int rA = wm * 64 + (l & 7) + ((l >> 3) & 1) * 8;
    const int bA = (l >> 4) & 1;
    const uint32_t wA   = (uint32_t)((bA ^ ((rA >> 1) & 3)) * 16);
    const uint32_t aRow = (uint32_t)(rA * ROWB);
    const int rB = wn * 32 + (l & 7) + ((l >> 4) & 1) * 8;
    const int bB = (l >> 3) & 1;
    const uint32_t wB   = (uint32_t)((bB ^ ((rB >> 1) & 3)) * 16);
    const uint32_t bRow = (uint32_t)(rB * ROWB);

    auto issue = [&](int kt, int buf) {
        const int kb = kt * BKB;
        const uint32_t s = sbase + (uint32_t)(buf * STGB);
#pragma unroll
        for (int p = 0; p < 2; p++) {
            const int r = p * 64 + lr;
            const uint32_t so = s + (uint32_t)(r * ROWB + ((c0 ^ ((r >> 1) & 3)) * 16));
            const size_t go = (size_t)r * KTOT + kb + c0 * 8;
            cp_async16_s(so,           gXh + go);
            cp_async16_s(so + PLB,     gXl + go);
            cp_async16_s(so + 2 * PLB, gBh + go);
            cp_async16_s(so + 3 * PLB, gBl + go);
        }
        cp_commit();
    };

    issue(0, 0);
    issue(1, 1);

    const int NKT = KTOT / BKB;   // 132
    int buf = 0;
    for (int kt = 0; kt < NKT; kt++) {
        if (kt == NKT - 1) cp_wait0(); else cp_wait1();
        __syncthreads();

        // Issue next stage BEFORE compute: stage (buf+2)%3 was last read in
        // iteration kt-1, already fenced by the barrier above. LSU work now
        // overlaps the MMA phase instead of serializing after it.
        if (kt + 2 < NKT) issue(kt + 2, (buf + 2) % NSTG);

        const uint32_t stg = sbase + (uint32_t)(buf * STGB);
        const uint32_t aH  = stg + aRow;
        const uint32_t aL  = aH + PLB;
        const uint32_t bH  = stg + 2 * PLB + bRow;
        const uint32_t bL  = bH + PLB;

#pragma unroll
        for (int ks = 0; ks < 2; ks++) {
            const uint32_t ka  = wA ^ (uint32_t)(ks << 5);
            const uint32_t kb_ = wB ^ (uint32_t)(ks << 5);
            uint32_t bh[4][2], bl[4][2];
            ldsm4(bh[0][0], bh[0][1], bh[1][0], bh[1][1], bH + kb_);
            ldsm4(bh[2][0], bh[2][1], bh[3][0], bh[3][1], bH + 1024 + kb_);
            ldsm4(bl[0][0], bl[0][1], bl[1][0], bl[1][1], bL + kb_);
            ldsm4(bl[2][0], bl[2][1], bl[3][0], bl[3][1], bL + 1024 + kb_);
#pragma unroll
            for (int mt = 0; mt < 4; mt++) {
                const uint32_t mtB = (uint32_t)(mt * 1024);
                uint32_t ah0, ah1, ah2, ah3, al0, al1, al2, al3;
                ldsm4(ah0, ah1, ah2, ah3, aH + mtB + ka);
                ldsm4(al0, al1, al2, al3, aL + mtB + ka);
#pragma unroll
                for (int nt = 0; nt < 4; nt++)
                    mma_bf16(acc[mt][nt], ah0, ah1, ah2, ah3, bh[nt][0], bh[nt][1]);
#pragma unroll
                for (int nt = 0; nt < 4; nt++)
                    mma_bf16(acc[mt][nt], al0, al1, al2, al3, bh[nt][0], bh[nt][1]);
#pragma unroll
                for (int nt = 0; nt < 4; nt++)
                    mma_bf16(acc[mt][nt], ah0, ah1, ah2, ah3, bl[nt][0], bl[nt][1]);
            }
        }

        buf = (buf + 1) % NSTG;
    }

    // Epilogue: add bias, write out
#pragma unroll
    for (int mt = 0; mt < 4; mt++) {
        const int row = m0 + wm * 64 + mt * 16 + g;
#pragma unroll
        for (int nt = 0; nt < 4; nt++) {
            const int col = n0 + wn * 32 + nt * 8 + 2 * tig;
            const float b0 = __ldg(&bias[col]);
            const float b1 = __ldg(&bias[col + 1]);
            float2 v0 = make_float2(acc[mt][nt][0] + b0, acc[mt][nt][1] + b1);
            float2 v1 = make_float2(acc[mt][nt][2] + b0, acc[mt][nt][3] + b1);
            *(float2*)&out[(size_t)row * D + col]       = v0;
            *(float2*)&out[(size_t)(row + 8) * D + col] = v1;
        }
    }
}

// ---------------------------------------------------------------------------
// Launch
// ---------------------------------------------------------------------------
extern "C" void kernel_launch(void* const* d_in, const int* in_sizes, int n_in,
                              void* d_out, int out_size) {
    const float* x     = (const float*)d_in[0];   // [4,2048,4096]
    const float* loraA = (const float*)d_in[1];   // [8,16,4096]
    const float* loraB = (const float*)d_in[2];   // [8,4096,16]
    const float* W     = (const float*)d_in[3];   // [4096,4096]
    const float* bias  = (const float*)d_in[4];   // [4096]
    const float* lw    = (const float*)d_in[5];   // [8]
    float* out = (float*)d_out;

    static bool attr_set = false;
    if (!attr_set) {
        cudaFuncSetAttribute(gemm_mainp, cudaFuncAttributeMaxDynamicSharedMemorySize,
                             SMEM_MAIN);
        attr_set = true;
    }

    gemm_h   <<<dim3(KS, MTOK / BM), 256>>>(x, loraA, lw);
    convert_x<<<(int)((size_t)MTOK * KTOT / 4 / 256), 256>>>(x);
    convert_b<<<(int)((size_t)D * KTOT / 4 / 256), 256>>>(W, loraB);
    gemm_mainp<<<dim3(D / BN, MTOK / BM), 256, SMEM_MAIN>>>(bias, out);
}

// round 16
// speedup vs baseline: 1.3046x; 1.3046x over previous
#include <cuda_runtime.h>
#include <cuda_bf16.h>
#include <cstdint>

// ---------------------------------------------------------------------------
// Problem constants
// ---------------------------------------------------------------------------
#define MTOK   8192          // B_*S tokens
#define D      4096
#define NADAPT 8
#define RANK   16
#define NR     128           // NADAPT*RANK
#define KTOT   4224          // D + NR, concatenated GEMM K
#define LSCALE 2.0f          // ALPHA/RANK
#define KS     4             // K-split factor for gemm_h

// ---------------------------------------------------------------------------
// Global scratch (static __device__ arrays: allocation-guard-safe)
// ---------------------------------------------------------------------------
__device__ __align__(128) float          g_Hp[KS * MTOK * NR];
__device__ __align__(128) __nv_bfloat16  g_Xh[(size_t)MTOK * KTOT];
__device__ __align__(128) __nv_bfloat16  g_Xl[(size_t)MTOK * KTOT];
__device__ __align__(128) __nv_bfloat16  g_Bh[(size_t)D    * KTOT];
__device__ __align__(128) __nv_bfloat16  g_Bl[(size_t)D    * KTOT];

// ---------------------------------------------------------------------------
// Helpers
// ---------------------------------------------------------------------------
__device__ __forceinline__ void cp_async16(void* smem, const void* gmem) {
    uint32_t sa = (uint32_t)__cvta_generic_to_shared(smem);
    asm volatile("cp.async.cg.shared.global [%0], [%1], 16;\n" :: "r"(sa), "l"(gmem));
}
__device__ __forceinline__ void cp_async16_s(uint32_t sa, const void* gmem) {
    asm volatile("cp.async.cg.shared.global [%0], [%1], 16;\n" :: "r"(sa), "l"(gmem));
}
__device__ __forceinline__ void cp_commit() { asm volatile("cp.async.commit_group;\n"); }
__device__ __forceinline__ void cp_wait0()  { asm volatile("cp.async.wait_group 0;\n"); }
__device__ __forceinline__ void cp_wait1()  { asm volatile("cp.async.wait_group 1;\n"); }

// bf16 split of two fp32 values: hi = truncate-to-bf16 (exact residual), lo = rn-bf16.
__device__ __forceinline__ void split2(float f0, float f1, uint32_t& hi, uint32_t& lo) {
    uint32_t u0 = __float_as_uint(f0), u1 = __float_as_uint(f1);
    asm("prmt.b32 %0, %1, %2, 0x7632;" : "=r"(hi) : "r"(u0), "r"(u1));
    float h0 = __uint_as_float(u0 & 0xffff0000u);
    float h1 = __uint_as_float(u1 & 0xffff0000u);
    float l0 = f0 - h0;
    float l1 = f1 - h1;
    asm("cvt.rn.bf16x2.f32 %0, %1, %2;" : "=r"(lo) : "f"(l1), "f"(l0));
}

__device__ __forceinline__ void mma_bf16(float c[4],
                                         uint32_t a0, uint32_t a1, uint32_t a2, uint32_t a3,
                                         uint32_t b0, uint32_t b1) {
    asm volatile(
        "mma.sync.aligned.m16n8k16.row.col.f32.bf16.bf16.f32 "
        "{%0,%1,%2,%3}, {%4,%5,%6,%7}, {%8,%9}, {%0,%1,%2,%3};\n"
        : "+f"(c[0]), "+f"(c[1]), "+f"(c[2]), "+f"(c[3])
        : "r"(a0), "r"(a1), "r"(a2), "r"(a3), "r"(b0), "r"(b1));
}

__device__ __forceinline__ void ldsm4(uint32_t& r0, uint32_t& r1, uint32_t& r2, uint32_t& r3,
                                      uint32_t addr) {
    asm volatile("ldmatrix.sync.aligned.m8n8.x4.shared.b16 {%0,%1,%2,%3}, [%4];"
                 : "=r"(r0), "=r"(r1), "=r"(r2), "=r"(r3) : "r"(addr));
}

// ---------------------------------------------------------------------------
// Kernel 1: H partial = (x @ A_all^T) * coef over a 1024-wide K slice
// grid (KS, 64), 256 threads (unchanged)
// ---------------------------------------------------------------------------
#define BM 128
#define BN 128
#define BK 16
#define SROW 24

__global__ __launch_bounds__(256)
void gemm_h(const float* __restrict__ X, const float* __restrict__ loraA,
            const float* __restrict__ lw) {
    __shared__ float Xs[2][BM * SROW];
    __shared__ float Ws[2][BN * SROW];

    const int tid = threadIdx.x;
    const int m0  = blockIdx.y * BM;
    const int ksp = blockIdx.x;
    const int wid = tid >> 5, lane = tid & 31;
    const int wm  = wid >> 2, wn = wid & 3;
    const int g   = lane >> 2, tig = lane & 3;

    float acc[4][4][4];
#pragma unroll
    for (int mt = 0; mt < 4; mt++)
#pragma unroll
        for (int nt = 0; nt < 4; nt++)
#pragma unroll
            for (int i = 0; i < 4; i++) acc[mt][nt][i] = 0.0f;

    const int lr = tid >> 2;
    const int lc = (tid & 3) * 4;

    auto issue = [&](int kt, int buf) {
        const float* ga = X + (size_t)m0 * D + kt * BK;
        const float* gb = loraA + kt * BK;
#pragma unroll
        for (int p = 0; p < 2; p++) {
            int r = p * 64 + lr;
            cp_async16(&Xs[buf][r * SROW + lc], ga + (size_t)r * D + lc);
            cp_async16(&Ws[buf][r * SROW + lc], gb + (size_t)r * D + lc);
        }
        cp_commit();
    };

    const int kt0 = ksp * (D / BK / KS);
    const int kt1 = kt0 + (D / BK / KS);

    issue(kt0, 0);
    cp_wait0();
    __syncthreads();

    for (int kt = kt0; kt < kt1; kt++) {
        const int cur = kt & 1;
        if (kt + 1 < kt1) issue(kt + 1, cur ^ 1);

        const float* Xc = Xs[cur];
        const float* Wc = Ws[cur];
        uint32_t bh[4][2], bl[4][2];
#pragma unroll
        for (int nt = 0; nt < 4; nt++) {
            const float* bb = &Wc[(wn * 32 + nt * 8 + g) * SROW + 2 * tig];
            float2 v0 = *(const float2*)bb;
            float2 v1 = *(const float2*)(bb + 8);
            split2(v0.x, v0.y, bh[nt][0], bl[nt][0]);
            split2(v1.x, v1.y, bh[nt][1], bl[nt][1]);
        }
#pragma unroll
        for (int mt = 0; mt < 4; mt++) {
            const float* ar = &Xc[(wm * 64 + mt * 16 + g) * SROW + 2 * tig];
            float2 u0 = *(const float2*)ar;
            float2 u1 = *(const float2*)(ar + 8 * SROW);
            float2 u2 = *(const float2*)(ar + 8);
            float2 u3 = *(const float2*)(ar + 8 * SROW + 8);
            uint32_t ah[4], al[4];
            split2(u0.x, u0.y, ah[0], al[0]);
            split2(u1.x, u1.y, ah[1], al[1]);
            split2(u2.x, u2.y, ah[2], al[2]);
            split2(u3.x, u3.y, ah[3], al[3]);
#pragma unroll
            for (int nt = 0; nt < 4; nt++)
                mma_bf16(acc[mt][nt], ah[0], ah[1], ah[2], ah[3], bh[nt][0], bh[nt][1]);
#pragma unroll
            for (int nt = 0; nt < 4; nt++)
                mma_bf16(acc[mt][nt], al[0], al[1], al[2], al[3], bh[nt][0], bh[nt][1]);
#pragma unroll
            for (int nt = 0; nt < 4; nt++)
                mma_bf16(acc[mt][nt], ah[0], ah[1], ah[2], ah[3], bl[nt][0], bl[nt][1]);
        }
        cp_wait0();
        __syncthreads();
    }

    float* Hp = g_Hp + (size_t)ksp * MTOK * NR;
#pragma unroll
    for (int mt = 0; mt < 4; mt++) {
        const int row = m0 + wm * 64 + mt * 16 + g;
#pragma unroll
        for (int nt = 0; nt < 4; nt++) {
            const int col = wn * 32 + nt * 8 + 2 * tig;
            const float c = LSCALE * __ldg(&lw[col >> 4]);
            float2 v0 = make_float2(acc[mt][nt][0] * c, acc[mt][nt][1] * c);
            float2 v1 = make_float2(acc[mt][nt][2] * c, acc[mt][nt][3] * c);
            *(float2*)&Hp[(size_t)row * NR + col]       = v0;
            *(float2*)&Hp[(size_t)(row + 8) * NR + col] = v1;
        }
    }
}

// ---------------------------------------------------------------------------
// Kernel 2: convert [x | sum(Hp)] -> g_Xh / g_Xl
// ---------------------------------------------------------------------------
__global__ __launch_bounds__(256)
void convert_x(const float* __restrict__ x) {
    size_t idx = (size_t)blockIdx.x * 256 + threadIdx.x;
    size_t e   = idx * 4;
    int m = (int)(e / KTOT);
    int k = (int)(e % KTOT);
    float4 v;
    if (k < D) {
        v = *(const float4*)&x[(size_t)m * D + k];
    } else {
        size_t off = (size_t)m * NR + (k - D);
        float4 p0 = *(const float4*)&g_Hp[off];
        float4 p1 = *(const float4*)&g_Hp[(size_t)1 * MTOK * NR + off];
        float4 p2 = *(const float4*)&g_Hp[(size_t)2 * MTOK * NR + off];
        float4 p3 = *(const float4*)&g_Hp[(size_t)3 * MTOK * NR + off];
        v.x = (p0.x + p1.x) + (p2.x + p3.x);
        v.y = (p0.y + p1.y) + (p2.y + p3.y);
        v.z = (p0.z + p1.z) + (p2.z + p3.z);
        v.w = (p0.w + p1.w) + (p2.w + p3.w);
    }
    uint32_t h0, l0, h1, l1;
    split2(v.x, v.y, h0, l0);
    split2(v.z, v.w, h1, l1);
    *(uint2*)&g_Xh[(size_t)m * KTOT + k] = make_uint2(h0, h1);
    *(uint2*)&g_Xl[(size_t)m * KTOT + k] = make_uint2(l0, l1);
}

// ---------------------------------------------------------------------------
// Kernel 3: convert [W | B_all] -> g_Bh / g_Bl
// ---------------------------------------------------------------------------
__global__ __launch_bounds__(256)
void convert_b(const float* __restrict__ W, const float* __restrict__ loraB) {
    size_t idx = (size_t)blockIdx.x * 256 + threadIdx.x;
    size_t e   = idx * 4;
    int n = (int)(e / KTOT);
    int k = (int)(e % KTOT);
    float4 v;
    if (k < D) {
        v = *(const float4*)&W[(size_t)n * D + k];
    } else {
        int na = (k - D) >> 4;
        int r  = (k - D) & 15;
        v = *(const float4*)&loraB[((size_t)na * D + n) * RANK + r];
    }
    uint32_t h0, l0, h1, l1;
    split2(v.x, v.y, h0, l0);
    split2(v.z, v.w, h1, l1);
    *(uint2*)&g_Bh[(size_t)n * KTOT + k] = make_uint2(h0, h1);
    *(uint2*)&g_Bl[(size_t)n * KTOT + k] = make_uint2(l0, l1);
}

// ---------------------------------------------------------------------------
// Kernel 4: main GEMM, 3-stage cp.async pipeline + XOR swizzle.
//   Single barrier per iteration, issue AFTER compute (short live ranges):
//     wait_group(1) -> syncthreads -> compute(kt) -> issue(kt+2)
//   Safety: any thread past the top barrier of iter kt has finished iter
//   kt-1 entirely; stage (buf+2)%3's last readers were iter kt-1, so the
//   cp.async writes cannot race LDSM reads. __launch_bounds__(256,2)
//   guarantees 2 CTA/SM (the R14 regression was regs 133 -> 1 CTA/SM).
// ---------------------------------------------------------------------------
#define BKB    32
#define ROWB   64                         // bytes per row (32 bf16)
#define PLB    (128 * ROWB)               // 8192 B per plane
#define STGB   (4 * PLB)                  // 32768 B per stage
#define NSTG   3
#define SMEM_MAIN (NSTG * STGB)           // 98304 bytes

__global__ __launch_bounds__(256, 2)
void gemm_mainp(const float* __restrict__ bias, float* __restrict__ out) {
    extern __shared__ __align__(128) char sm[];
    const uint32_t sbase = (uint32_t)__cvta_generic_to_shared(sm);

    const int tid = threadIdx.x;
    const int m0  = blockIdx.y * BM;
    const int n0  = blockIdx.x * BN;
    const int wid = tid >> 5, lane = tid & 31;
    const int wm  = wid >> 2, wn = wid & 3;
    const int g   = lane >> 2, tig = lane & 3;

    float acc[4][4][4];
#pragma unroll
    for (int mt = 0; mt < 4; mt++)
#pragma unroll
        for (int nt = 0; nt < 4; nt++)
#pragma unroll
            for (int i = 0; i < 4; i++) acc[mt][nt][i] = 0.0f;

    const int lr = tid >> 2;           // 0..63 row (2 passes -> 128)
    const int c0 = tid & 3;            // 16B chunk index within 64B row

    const __nv_bfloat16* gXh = g_Xh + (size_t)m0 * KTOT;
    const __nv_bfloat16* gXl = g_Xl + (size_t)m0 * KTOT;
    const __nv_bfloat16* gBh = g_Bh + (size_t)n0 * KTOT;
    const __nv_bfloat16* gBl = g_Bl + (size_t)n0 * KTOT;

    // LDSM lane addressing (swizzled). p(r) = (r>>1)&3 invariant under +16/+64.
    const int l  = lane;
    const int rA = wm * 64 + (l & 7) + ((l >> 3) & 1) * 8;
    const int bA = (l >> 4) & 1;
    const uint32_t wA   = (uint32_t)((bA ^ ((rA >> 1) & 3)) * 16);
    const uint32_t aRow = (uint32_t)(rA * ROWB);
    const int rB = wn * 32 + (l & 7) + ((l >> 4) & 1) * 8;
    const int bB = (l >> 3) & 1;
    const uint32_t wB   = (uint32_t)((bB ^ ((rB >> 1) & 3)) * 16);
    const uint32_t bRow = (uint32_t)(rB * ROWB);

    auto issue = [&](int kt, int buf) {
        const int kb = kt * BKB;
        const uint32_t s = sbase + (uint32_t)(buf * STGB);
#pragma unroll
        for (int p = 0; p < 2; p++) {
            const int r = p * 64 + lr;
            const uint32_t so = s + (uint32_t)(r * ROWB + ((c0 ^ ((r >> 1) & 3)) * 16));
            const size_t go = (size_t)r * KTOT + kb + c0 * 8;
            cp_async16_s(so,           gXh + go);
            cp_async16_s(so + PLB,     gXl + go);
            cp_async16_s(so + 2 * PLB, gBh + go);
            cp_async16_s(so + 3 * PLB, gBl + go);
        }
        cp_commit();
    };

    issue(0, 0);
    issue(1, 1);

    const int NKT = KTOT / BKB;   // 132
    int buf = 0;
    for (int kt = 0; kt < NKT; kt++) {
        if (kt == NKT - 1) cp_wait0(); else cp_wait1();
        __syncthreads();

        const uint32_t stg = sbase + (uint32_t)(buf * STGB);
        const uint32_t aH  = stg + aRow;
        const uint32_t aL  = aH + PLB;
        const uint32_t bH  = stg + 2 * PLB + bRow;
        const uint32_t bL  = bH + PLB;

#pragma unroll
        for (int ks = 0; ks < 2; ks++) {
            const uint32_t ka  = wA ^ (uint32_t)(ks << 5);
            const uint32_t kb_ = wB ^ (uint32_t)(ks << 5);
            uint32_t bh[4][2], bl[4][2];
            ldsm4(bh[0][0], bh[0][1], bh[1][0], bh[1][1], bH + kb_);
            ldsm4(bh[2][0], bh[2][1], bh[3][0], bh[3][1], bH + 1024 + kb_);
            ldsm4(bl[0][0], bl[0][1], bl[1][0], bl[1][1], bL + kb_);
            ldsm4(bl[2][0], bl[2][1], bl[3][0], bl[3][1], bL + 1024 + kb_);
#pragma unroll
            for (int mt = 0; mt < 4; mt++) {
                const uint32_t mtB = (uint32_t)(mt * 1024);
                uint32_t ah0, ah1, ah2, ah3, al0, al1, al2, al3;
                ldsm4(ah0, ah1, ah2, ah3, aH + mtB + ka);
                ldsm4(al0, al1, al2, al3, aL + mtB + ka);
#pragma unroll
                for (int nt = 0; nt < 4; nt++)
                    mma_bf16(acc[mt][nt], ah0, ah1, ah2, ah3, bh[nt][0], bh[nt][1]);
#pragma unroll
                for (int nt = 0; nt < 4; nt++)
                    mma_bf16(acc[mt][nt], al0, al1, al2, al3, bh[nt][0], bh[nt][1]);
#pragma unroll
                for (int nt = 0; nt < 4; nt++)
                    mma_bf16(acc[mt][nt], ah0, ah1, ah2, ah3, bl[nt][0], bl[nt][1]);
            }
        }

        // Issue next stage AFTER compute (no barrier needed: the top barrier
        // of this iteration already ordered all of iter kt-1's reads of
        // stage (buf+2)%3 before these writes). Address regs stay short-lived.
        if (kt + 2 < NKT) issue(kt + 2, (buf + 2) % NSTG);

        buf = (buf + 1) % NSTG;
    }

    // Epilogue: add bias, write out
#pragma unroll
    for (int mt = 0; mt < 4; mt++) {
        const int row = m0 + wm * 64 + mt * 16 + g;
#pragma unroll
        for (int nt = 0; nt < 4; nt++) {
            const int col = n0 + wn * 32 + nt * 8 + 2 * tig;
            const float b0 = __ldg(&bias[col]);
            const float b1 = __ldg(&bias[col + 1]);
            float2 v0 = make_float2(acc[mt][nt][0] + b0, acc[mt][nt][1] + b1);
            float2 v1 = make_float2(acc[mt][nt][2] + b0, acc[mt][nt][3] + b1);
            *(float2*)&out[(size_t)row * D + col]       = v0;
            *(float2*)&out[(size_t)(row + 8) * D + col] = v1;
        }
    }
}

// ---------------------------------------------------------------------------
// Launch
// ---------------------------------------------------------------------------
extern "C" void kernel_launch(void* const* d_in, const int* in_sizes, int n_in,
                              void* d_out, int out_size) {
    const float* x     = (const float*)d_in[0];   // [4,2048,4096]
    const float* loraA = (const float*)d_in[1];   // [8,16,4096]
    const float* loraB = (const float*)d_in[2];   // [8,4096,16]
    const float* W     = (const float*)d_in[3];   // [4096,4096]
    const float* bias  = (const float*)d_in[4];   // [4096]
    const float* lw    = (const float*)d_in[5];   // [8]
    float* out = (float*)d_out;

    static bool attr_set = false;
    if (!attr_set) {
        cudaFuncSetAttribute(gemm_mainp, cudaFuncAttributeMaxDynamicSharedMemorySize,
                             SMEM_MAIN);
        attr_set = true;
    }

    gemm_h   <<<dim3(KS, MTOK / BM), 256>>>(x, loraA, lw);
    convert_x<<<(int)((size_t)MTOK * KTOT / 4 / 256), 256>>>(x);
    convert_b<<<(int)((size_t)D * KTOT / 4 / 256), 256>>>(W, loraB);
    gemm_mainp<<<dim3(D / BN, MTOK / BM), 256, SMEM_MAIN>>>(bias, out);
}